// round 2
// baseline (speedup 1.0000x reference)
#include <cuda_runtime.h>

#define BB 4
#define NN 256
#define CC 512
#define HH 8
#define DD 64

// Scratch (allocation-free rule: device globals)
__device__ float g_Q[BB*NN*CC];
__device__ float g_K[BB*NN*CC];
__device__ float g_V[BB*NN*CC];
__device__ float g_S[BB*HH*NN*NN];   // [b][h][i][j] clamped score sums -> softmax weights

__device__ __forceinline__ unsigned f2tf(float x){
    unsigned r; asm("cvt.rna.tf32.f32 %0, %1;" : "=r"(r) : "f"(x)); return r;
}

__device__ __forceinline__ void mma8(float* c, const unsigned* a, const unsigned* b){
    asm volatile("mma.sync.aligned.m16n8k8.row.col.f32.tf32.tf32.f32 "
        "{%0,%1,%2,%3}, {%4,%5,%6,%7}, {%8,%9}, {%0,%1,%2,%3};\n"
        : "+f"(c[0]), "+f"(c[1]), "+f"(c[2]), "+f"(c[3])
        : "r"(a[0]), "r"(a[1]), "r"(a[2]), "r"(a[3]), "r"(b[0]), "r"(b[1]));
}

// C[M,512] = A[M,512] @ W[512,512], tf32 tensor cores.
// Grid: blockIdx.x = n-tile (FAST axis -> 4 n-tiles of one m-tile co-resident,
// A tile read once from DRAM, 3x L2 hits), blockIdx.y = m-tile.
// EPI==0: plain store (QKV projections). SPLIT==1 adds 3xtf32 compensation.
// EPI==1: fused attention epilogue: val = acc * Q[b,i,c] * K[b,j,c] / 8,
//         store e_out, reduce per-(row,head) sums (clamped) into g_S.
// Block tile 128x128, 256 threads (8 warps as 2x4), warp tile 64x32.
template<int EPI, int SPLIT>
__global__ void __launch_bounds__(256, 2)
gemm_tf32(const float* __restrict__ A, const float* __restrict__ W,
          float* __restrict__ C)
{
    constexpr int BK = SPLIT ? 16 : 32;
    extern __shared__ unsigned sm[];
    unsigned* AsH = sm;                    // [BK][132] k-major (conflict-free frag loads)
    unsigned* BsH = AsH + BK*132;          // [BK][132]
    unsigned* AsL = BsH + BK*132;          // SPLIT only
    unsigned* BsL = AsL + BK*132;
    float* rs = (float*)(sm + 2*32*132);   // EPI only: 128 rows x 2 heads

    const int tid  = threadIdx.x;
    const int lane = tid & 31;
    const int wid  = tid >> 5;
    const int wm = wid >> 2, wn = wid & 3;     // 2 x 4 warp grid
    const int lr = lane >> 2, lc = lane & 3;   // groupID, tid-in-group
    const int m0 = blockIdx.y * 128;
    const int n0 = blockIdx.x * 128;

    float acc[4][4][4];
    #pragma unroll
    for (int a=0;a<4;a++)
        #pragma unroll
        for (int b=0;b<4;b++)
            #pragma unroll
            for (int c=0;c<4;c++) acc[a][b][c]=0.f;

    for (int kb = 0; kb < 512; kb += BK) {
        // ---- A tile [128][BK] -> AsH[k][row] (transposed) ----
        #pragma unroll
        for (int l = 0; l < BK/8; l++) {
            int idx = l*256 + tid;
            int row = idx / (BK/4);
            int kq  = idx % (BK/4);
            float4 v = *(const float4*)(A + (size_t)(m0+row)*512 + kb + kq*4);
            float vv[4] = {v.x, v.y, v.z, v.w};
            #pragma unroll
            for (int c = 0; c < 4; c++) {
                unsigned hi = f2tf(vv[c]);
                AsH[(kq*4+c)*132 + row] = hi;
                if (SPLIT) AsL[(kq*4+c)*132 + row] = f2tf(vv[c] - __uint_as_float(hi));
            }
        }
        // ---- W tile [BK][128] -> BsH[k][col] ----
        #pragma unroll
        for (int l = 0; l < BK/8; l++) {
            int idx = l*256 + tid;
            int k  = idx >> 5;
            int cq = idx & 31;
            float4 v = *(const float4*)(W + (size_t)(kb+k)*512 + n0 + cq*4);
            float vv[4] = {v.x, v.y, v.z, v.w};
            #pragma unroll
            for (int c = 0; c < 4; c++) {
                unsigned hi = f2tf(vv[c]);
                BsH[k*132 + cq*4 + c] = hi;
                if (SPLIT) BsL[k*132 + cq*4 + c] = f2tf(vv[c] - __uint_as_float(hi));
            }
        }
        __syncthreads();
        #pragma unroll
        for (int k8 = 0; k8 < BK/8; k8++) {
            const int kk = k8*8 + lc;
            unsigned af[4][4], bf[4][2];
            #pragma unroll
            for (int mt=0; mt<4; mt++) {
                int r = wm*64 + mt*16 + lr;
                af[mt][0] = AsH[kk*132 + r];
                af[mt][1] = AsH[kk*132 + r + 8];
                af[mt][2] = AsH[(kk+4)*132 + r];
                af[mt][3] = AsH[(kk+4)*132 + r + 8];
            }
            #pragma unroll
            for (int nt=0; nt<4; nt++) {
                int c = wn*32 + nt*8 + lr;
                bf[nt][0] = BsH[kk*132 + c];
                bf[nt][1] = BsH[(kk+4)*132 + c];
            }
            #pragma unroll
            for (int mt=0; mt<4; mt++)
                #pragma unroll
                for (int nt=0; nt<4; nt++)
                    mma8(acc[mt][nt], af[mt], bf[nt]);
            if (SPLIT) {
                unsigned afl[4][4], bfl[4][2];
                #pragma unroll
                for (int mt=0; mt<4; mt++) {
                    int r = wm*64 + mt*16 + lr;
                    afl[mt][0] = AsL[kk*132 + r];
                    afl[mt][1] = AsL[kk*132 + r + 8];
                    afl[mt][2] = AsL[(kk+4)*132 + r];
                    afl[mt][3] = AsL[(kk+4)*132 + r + 8];
                }
                #pragma unroll
                for (int nt=0; nt<4; nt++) {
                    int c = wn*32 + nt*8 + lr;
                    bfl[nt][0] = BsL[kk*132 + c];
                    bfl[nt][1] = BsL[(kk+4)*132 + c];
                }
                #pragma unroll
                for (int mt=0; mt<4; mt++)
                    #pragma unroll
                    for (int nt=0; nt<4; nt++) {
                        mma8(acc[mt][nt], af[mt],  bfl[nt]);
                        mma8(acc[mt][nt], afl[mt], bf[nt]);
                    }
            }
        }
        __syncthreads();
    }

    if (EPI == 0) {
        #pragma unroll
        for (int mt=0; mt<4; mt++){
            int r = m0 + wm*64 + mt*16 + lr;
            #pragma unroll
            for (int nt=0; nt<4; nt++){
                int c = n0 + wn*32 + nt*8 + lc*2;
                *(float2*)(C + (size_t)r*512 + c)     = make_float2(acc[mt][nt][0], acc[mt][nt][1]);
                *(float2*)(C + (size_t)(r+8)*512 + c) = make_float2(acc[mt][nt][2], acc[mt][nt][3]);
            }
        }
    } else {
        rs[tid] = 0.f;
        __syncthreads();
        // 128 consecutive rows stay within one (b,i); j = j0 + local_row.
        const int bidx = m0 >> 16;
        const int ii   = (m0 >> 8) & 255;
        const int j0   = m0 & 255;
        const float* Qrow = g_Q + (size_t)(bidx*256 + ii)*512;
        const float* Kb   = g_K + (size_t)bidx*256*512;
        float qv[4][2];
        #pragma unroll
        for (int nt=0; nt<4; nt++){
            int c = n0 + wn*32 + nt*8 + lc*2;
            qv[nt][0] = Qrow[c]   * 0.125f;
            qv[nt][1] = Qrow[c+1] * 0.125f;
        }
        const int hl = wn >> 1;   // each warp's 32 cols live in one head
        #pragma unroll
        for (int mt=0; mt<4; mt++){
            int rlA = wm*64 + mt*16 + lr;
            int rlB = rlA + 8;
            const float* KrA = Kb + (size_t)(j0 + rlA)*512;
            const float* KrB = Kb + (size_t)(j0 + rlB)*512;
            float pA = 0.f, pB = 0.f;
            #pragma unroll
            for (int nt=0; nt<4; nt++){
                int c = n0 + wn*32 + nt*8 + lc*2;
                float v0 = acc[mt][nt][0] * qv[nt][0] * KrA[c];
                float v1 = acc[mt][nt][1] * qv[nt][1] * KrA[c+1];
                float v2 = acc[mt][nt][2] * qv[nt][0] * KrB[c];
                float v3 = acc[mt][nt][3] * qv[nt][1] * KrB[c+1];
                *(float2*)(C + (size_t)(m0+rlA)*512 + c) = make_float2(v0, v1);
                *(float2*)(C + (size_t)(m0+rlB)*512 + c) = make_float2(v2, v3);
                pA += v0 + v1;
                pB += v2 + v3;
            }
            pA += __shfl_xor_sync(0xffffffffu, pA, 1);
            pA += __shfl_xor_sync(0xffffffffu, pA, 2);
            pB += __shfl_xor_sync(0xffffffffu, pB, 1);
            pB += __shfl_xor_sync(0xffffffffu, pB, 2);
            if (lc == 0) {
                atomicAdd(&rs[rlA*2 + hl], pA);
                atomicAdd(&rs[rlB*2 + hl], pB);
            }
        }
        __syncthreads();
        {
            int rl  = tid >> 1;
            int hl2 = tid & 1;
            int hh  = (n0 >> 6) + hl2;
            float sv = rs[tid];
            sv = fminf(fmaxf(sv, -5.f), 5.f);
            g_S[((size_t)(bidx*8 + hh)*256 + ii)*256 + j0 + rl] = sv;
        }
    }
}

// Per (b, h, 64-row i-tile): softmax over j of g_S row, then h_out = w @ V_head.
__global__ void __launch_bounds__(256)
softmax_av(float* __restrict__ hout)
{
    const int it = blockIdx.x;       // 0..3
    const int h  = blockIdx.y;       // 0..7
    const int b  = blockIdx.z;       // 0..3
    const int i0 = it * 64;
    extern __shared__ float smf[];
    float* ws = smf;                 // [64][256]
    float* vs = smf + 64*256;        // [32][68]
    const int tid = threadIdx.x;

    const float* Sp = g_S + ((size_t)(b*8 + h)*256 + i0)*256;
    #pragma unroll
    for (int l = 0; l < 16; l++) {
        int idx = l*256 + tid;
        ((float4*)ws)[idx] = ((const float4*)Sp)[idx];
    }
    __syncthreads();

    const int wid = tid >> 5, lane = tid & 31;
    for (int r = wid*8; r < wid*8 + 8; r++) {
        float* row = ws + r*256;
        float v[8];
        float mx = -1e30f;
        #pragma unroll
        for (int e2=0;e2<8;e2++){ v[e2] = row[lane + e2*32]; mx = fmaxf(mx, v[e2]); }
        #pragma unroll
        for (int o=16;o;o>>=1) mx = fmaxf(mx, __shfl_xor_sync(0xffffffffu, mx, o));
        float s = 0.f;
        #pragma unroll
        for (int e2=0;e2<8;e2++){ v[e2] = __expf(v[e2] - mx); s += v[e2]; }
        #pragma unroll
        for (int o=16;o;o>>=1) s += __shfl_xor_sync(0xffffffffu, s, o);
        float inv = 1.f / s;
        #pragma unroll
        for (int e2=0;e2<8;e2++) row[lane + e2*32] = v[e2]*inv;
    }
    __syncthreads();

    const int tx = tid & 15, ty = tid >> 4;  // 16x16, 4x4 per thread
    float acc[4][4];
    #pragma unroll
    for (int p=0;p<4;p++)
        #pragma unroll
        for (int q=0;q<4;q++) acc[p][q]=0.f;

    const float* Vp = g_V + (size_t)b*256*512 + h*64;
    for (int kbv = 0; kbv < 256; kbv += 32) {
        #pragma unroll
        for (int l=0;l<2;l++){
            int idx = l*256 + tid;
            int kk = idx >> 4, dq = idx & 15;
            float4 vv = *(const float4*)(Vp + (size_t)(kbv+kk)*512 + dq*4);
            *(float4*)(vs + kk*68 + dq*4) = vv;
        }
        __syncthreads();
        #pragma unroll
        for (int k=0;k<32;k++){
            float a0 = ws[(ty*4+0)*256 + kbv + k];
            float a1 = ws[(ty*4+1)*256 + kbv + k];
            float a2 = ws[(ty*4+2)*256 + kbv + k];
            float a3 = ws[(ty*4+3)*256 + kbv + k];
            float4 vv = *(float4*)(vs + k*68 + tx*4);
            acc[0][0] += a0*vv.x; acc[0][1] += a0*vv.y; acc[0][2] += a0*vv.z; acc[0][3] += a0*vv.w;
            acc[1][0] += a1*vv.x; acc[1][1] += a1*vv.y; acc[1][2] += a1*vv.z; acc[1][3] += a1*vv.w;
            acc[2][0] += a2*vv.x; acc[2][1] += a2*vv.y; acc[2][2] += a2*vv.z; acc[2][3] += a2*vv.w;
            acc[3][0] += a3*vv.x; acc[3][1] += a3*vv.y; acc[3][2] += a3*vv.z; acc[3][3] += a3*vv.w;
        }
        __syncthreads();
    }

    float* outp = hout + (size_t)(b*256 + i0)*512 + h*64;
    #pragma unroll
    for (int p=0;p<4;p++){
        int r = ty*4 + p;
        *(float4*)(outp + (size_t)r*512 + tx*4) =
            make_float4(acc[p][0], acc[p][1], acc[p][2], acc[p][3]);
    }
}

extern "C" void kernel_launch(void* const* d_in, const int* in_sizes, int n_in,
                              void* d_out, int out_size)
{
    const float* h  = (const float*)d_in[0];
    const float* e  = (const float*)d_in[1];
    const float* Wq = (const float*)d_in[2];
    const float* Wk = (const float*)d_in[3];
    const float* Wv = (const float*)d_in[4];
    const float* We = (const float*)d_in[5];
    float* outp  = (float*)d_out;
    float* h_out = outp;                               // [B,N,H*D]
    float* e_out = outp + (size_t)BB*NN*CC;            // [B,N,N,H*D]

    float *pQ, *pK, *pV;
    cudaGetSymbolAddress((void**)&pQ, g_Q);
    cudaGetSymbolAddress((void**)&pK, g_K);
    cudaGetSymbolAddress((void**)&pV, g_V);

    cudaFuncSetAttribute(softmax_av, cudaFuncAttributeMaxDynamicSharedMemorySize, 75776);

    const size_t gs = 34816;   // 2*32*132 u32 tiles + 1 KB row sums
    dim3 qg(4, 8);             // x = n-tiles (4), y = m-tiles (8) ; M=1024, N=512
    gemm_tf32<0,1><<<qg, 256, gs>>>(h, Wq, pQ);
    gemm_tf32<0,1><<<qg, 256, gs>>>(h, Wk, pK);
    gemm_tf32<0,1><<<qg, 256, gs>>>(h, Wv, pV);

    dim3 mg(4, 2048);          // x = n-tiles (4), y = m-tiles (2048)
    gemm_tf32<1,0><<<mg, 256, gs>>>(e, We, e_out);

    dim3 ag(4, 8, 4);
    softmax_av<<<ag, 256, 75776>>>(h_out);
}

// round 3
// speedup vs baseline: 1.1731x; 1.1731x over previous
#include <cuda_runtime.h>

#define BB 4
#define NN 256
#define CC 512
#define HH 8
#define DD 64

// Scratch (allocation-free rule: device globals)
__device__ float g_Q[BB*NN*CC];
__device__ float g_K[BB*NN*CC];
__device__ float g_V[BB*NN*CC];
__device__ float g_S[BB*HH*NN*NN];   // [b][h][i][j] clamped score sums -> softmax weights

__device__ __forceinline__ unsigned f2tf(float x){
    unsigned r; asm("cvt.rna.tf32.f32 %0, %1;" : "=r"(r) : "f"(x)); return r;
}

__device__ __forceinline__ void mma8(float* c, const unsigned* a, const unsigned* b){
    asm volatile("mma.sync.aligned.m16n8k8.row.col.f32.tf32.tf32.f32 "
        "{%0,%1,%2,%3}, {%4,%5,%6,%7}, {%8,%9}, {%0,%1,%2,%3};\n"
        : "+f"(c[0]), "+f"(c[1]), "+f"(c[2]), "+f"(c[3])
        : "r"(a[0]), "r"(a[1]), "r"(a[2]), "r"(a[3]), "r"(b[0]), "r"(b[1]));
}

// C[M,512] = A[M,512] @ W[512,512], tf32 tensor cores.
// Grid: blockIdx.x = n-tile (FAST axis -> 4 n-tiles of one m-tile co-resident,
// A tile read once from DRAM, 3x L2 hits), blockIdx.y = m-tile.
// Smem layout: k-major [k][136] with XOR swizzle col' = col ^ (GM*(k>>2)),
// GM = 4 (BK=32) / 8 (BK=16). Stride 136 = 8 mod 32 + swizzle makes BOTH the
// transpose stores and all fragment loads bank-conflict-free (R2 fix: the old
// [k][132] layout had 8-way store conflicts + 2-way load conflicts -> l1tex 89.7%).
// EPI==0: plain store (QKV projections). SPLIT==1 adds 3xtf32 compensation.
// EPI==1: fused attention epilogue: val = acc * Q[b,i,c] * K[b,j,c] / 8,
//         store e_out, reduce per-(row,head) sums (clamped) into g_S.
// Block tile 128x128, 256 threads (8 warps as 2x4), warp tile 64x32.
template<int EPI, int SPLIT>
__global__ void __launch_bounds__(256, 2)
gemm_tf32(const float* __restrict__ A, const float* __restrict__ W,
          float* __restrict__ C)
{
    constexpr int BK = SPLIT ? 16 : 32;
    constexpr int GM = SPLIT ? 8 : 4;      // swizzle multiplier
    constexpr int LDK = 136;               // words per k-row (136 % 32 == 8)
    extern __shared__ unsigned sm[];
    unsigned* AsH = sm;                    // [BK][LDK]
    unsigned* BsH = AsH + BK*LDK;
    unsigned* AsL = BsH + BK*LDK;          // SPLIT only
    unsigned* BsL = AsL + BK*LDK;
    float* rs = (float*)(sm + 2*32*LDK);   // EPI only: 128 rows x 2 heads

    const int tid  = threadIdx.x;
    const int lane = tid & 31;
    const int wid  = tid >> 5;
    const int wm = wid >> 2, wn = wid & 3;     // 2 x 4 warp grid
    const int lr = lane >> 2, lc = lane & 3;   // groupID, tid-in-group
    const int m0 = blockIdx.y * 128;
    const int n0 = blockIdx.x * 128;

    float acc[4][4][4];
    #pragma unroll
    for (int a=0;a<4;a++)
        #pragma unroll
        for (int b=0;b<4;b++)
            #pragma unroll
            for (int c=0;c<4;c++) acc[a][b][c]=0.f;

    for (int kb = 0; kb < 512; kb += BK) {
        // ---- A tile [128][BK] -> AsH[k][row^sw] (transposed, conflict-free) ----
        #pragma unroll
        for (int l = 0; l < BK/8; l++) {
            int idx = l*256 + tid;
            int row = idx / (BK/4);
            int kq  = idx % (BK/4);
            float4 v = *(const float4*)(A + (size_t)(m0+row)*512 + kb + kq*4);
            float vv[4] = {v.x, v.y, v.z, v.w};
            int sw = row ^ (GM*kq);            // k>>2 == kq for k = 4kq+c
            #pragma unroll
            for (int c = 0; c < 4; c++) {
                int k = kq*4 + c;
                unsigned hi = f2tf(vv[c]);
                AsH[k*LDK + sw] = hi;
                if (SPLIT) AsL[k*LDK + sw] = f2tf(vv[c] - __uint_as_float(hi));
            }
        }
        // ---- W tile [BK][128] -> BsH[k][col^sw], vectorized STS.128 ----
        #pragma unroll
        for (int l = 0; l < BK/8; l++) {
            int idx = l*256 + tid;
            int k  = idx >> 5;
            int cq = idx & 31;
            float4 v = *(const float4*)(W + (size_t)(kb+k)*512 + n0 + cq*4);
            int colb = (cq*4) ^ (GM*(k>>2));   // GM*(k>>2) multiple of 4 -> 16B aligned
            uint4 h4;
            h4.x = f2tf(v.x); h4.y = f2tf(v.y); h4.z = f2tf(v.z); h4.w = f2tf(v.w);
            *(uint4*)&BsH[k*LDK + colb] = h4;
            if (SPLIT) {
                uint4 l4;
                l4.x = f2tf(v.x - __uint_as_float(h4.x));
                l4.y = f2tf(v.y - __uint_as_float(h4.y));
                l4.z = f2tf(v.z - __uint_as_float(h4.z));
                l4.w = f2tf(v.w - __uint_as_float(h4.w));
                *(uint4*)&BsL[k*LDK + colb] = l4;
            }
        }
        __syncthreads();
        #pragma unroll
        for (int k8 = 0; k8 < BK/8; k8++) {
            const int kk = k8*8 + lc;
            const int g0 = GM * (kk >> 2);       // warp-constant (lc < 4)
            const int g1 = GM * ((kk+4) >> 2);
            unsigned af[4][4], bf[4][2];
            #pragma unroll
            for (int mt=0; mt<4; mt++) {
                int r = wm*64 + mt*16 + lr;
                af[mt][0] = AsH[kk*LDK     + (r       ^ g0)];
                af[mt][1] = AsH[kk*LDK     + ((r + 8) ^ g0)];
                af[mt][2] = AsH[(kk+4)*LDK + (r       ^ g1)];
                af[mt][3] = AsH[(kk+4)*LDK + ((r + 8) ^ g1)];
            }
            #pragma unroll
            for (int nt=0; nt<4; nt++) {
                int c = wn*32 + nt*8 + lr;
                bf[nt][0] = BsH[kk*LDK     + (c ^ g0)];
                bf[nt][1] = BsH[(kk+4)*LDK + (c ^ g1)];
            }
            #pragma unroll
            for (int mt=0; mt<4; mt++)
                #pragma unroll
                for (int nt=0; nt<4; nt++)
                    mma8(acc[mt][nt], af[mt], bf[nt]);
            if (SPLIT) {
                unsigned afl[4][4], bfl[4][2];
                #pragma unroll
                for (int mt=0; mt<4; mt++) {
                    int r = wm*64 + mt*16 + lr;
                    afl[mt][0] = AsL[kk*LDK     + (r       ^ g0)];
                    afl[mt][1] = AsL[kk*LDK     + ((r + 8) ^ g0)];
                    afl[mt][2] = AsL[(kk+4)*LDK + (r       ^ g1)];
                    afl[mt][3] = AsL[(kk+4)*LDK + ((r + 8) ^ g1)];
                }
                #pragma unroll
                for (int nt=0; nt<4; nt++) {
                    int c = wn*32 + nt*8 + lr;
                    bfl[nt][0] = BsL[kk*LDK     + (c ^ g0)];
                    bfl[nt][1] = BsL[(kk+4)*LDK + (c ^ g1)];
                }
                #pragma unroll
                for (int mt=0; mt<4; mt++)
                    #pragma unroll
                    for (int nt=0; nt<4; nt++) {
                        mma8(acc[mt][nt], af[mt],  bfl[nt]);
                        mma8(acc[mt][nt], afl[mt], bf[nt]);
                    }
            }
        }
        __syncthreads();
    }

    if (EPI == 0) {
        #pragma unroll
        for (int mt=0; mt<4; mt++){
            int r = m0 + wm*64 + mt*16 + lr;
            #pragma unroll
            for (int nt=0; nt<4; nt++){
                int c = n0 + wn*32 + nt*8 + lc*2;
                *(float2*)(C + (size_t)r*512 + c)     = make_float2(acc[mt][nt][0], acc[mt][nt][1]);
                *(float2*)(C + (size_t)(r+8)*512 + c) = make_float2(acc[mt][nt][2], acc[mt][nt][3]);
            }
        }
    } else {
        rs[tid] = 0.f;
        __syncthreads();
        // 128 consecutive rows stay within one (b,i); j = j0 + local_row.
        const int bidx = m0 >> 16;
        const int ii   = (m0 >> 8) & 255;
        const int j0   = m0 & 255;
        const float* Qrow = g_Q + (size_t)(bidx*256 + ii)*512;
        const float* Kb   = g_K + (size_t)bidx*256*512;
        float qv[4][2];
        #pragma unroll
        for (int nt=0; nt<4; nt++){
            int c = n0 + wn*32 + nt*8 + lc*2;
            qv[nt][0] = Qrow[c]   * 0.125f;
            qv[nt][1] = Qrow[c+1] * 0.125f;
        }
        const int hl = wn >> 1;   // each warp's 32 cols live in one head
        #pragma unroll
        for (int mt=0; mt<4; mt++){
            int rlA = wm*64 + mt*16 + lr;
            int rlB = rlA + 8;
            const float* KrA = Kb + (size_t)(j0 + rlA)*512;
            const float* KrB = Kb + (size_t)(j0 + rlB)*512;
            float pA = 0.f, pB = 0.f;
            #pragma unroll
            for (int nt=0; nt<4; nt++){
                int c = n0 + wn*32 + nt*8 + lc*2;
                float v0 = acc[mt][nt][0] * qv[nt][0] * KrA[c];
                float v1 = acc[mt][nt][1] * qv[nt][1] * KrA[c+1];
                float v2 = acc[mt][nt][2] * qv[nt][0] * KrB[c];
                float v3 = acc[mt][nt][3] * qv[nt][1] * KrB[c+1];
                *(float2*)(C + (size_t)(m0+rlA)*512 + c) = make_float2(v0, v1);
                *(float2*)(C + (size_t)(m0+rlB)*512 + c) = make_float2(v2, v3);
                pA += v0 + v1;
                pB += v2 + v3;
            }
            pA += __shfl_xor_sync(0xffffffffu, pA, 1);
            pA += __shfl_xor_sync(0xffffffffu, pA, 2);
            pB += __shfl_xor_sync(0xffffffffu, pB, 1);
            pB += __shfl_xor_sync(0xffffffffu, pB, 2);
            if (lc == 0) {
                atomicAdd(&rs[rlA*2 + hl], pA);
                atomicAdd(&rs[rlB*2 + hl], pB);
            }
        }
        __syncthreads();
        {
            int rl  = tid >> 1;
            int hl2 = tid & 1;
            int hh  = (n0 >> 6) + hl2;
            float sv = rs[tid];
            sv = fminf(fmaxf(sv, -5.f), 5.f);
            g_S[((size_t)(bidx*8 + hh)*256 + ii)*256 + j0 + rl] = sv;
        }
    }
}

// Per (b, h, 64-row i-tile): softmax over j of g_S row, then h_out = w @ V_head.
__global__ void __launch_bounds__(256)
softmax_av(float* __restrict__ hout)
{
    const int it = blockIdx.x;       // 0..3
    const int h  = blockIdx.y;       // 0..7
    const int b  = blockIdx.z;       // 0..3
    const int i0 = it * 64;
    extern __shared__ float smf[];
    float* ws = smf;                 // [64][256]
    float* vs = smf + 64*256;        // [32][68]
    const int tid = threadIdx.x;

    const float* Sp = g_S + ((size_t)(b*8 + h)*256 + i0)*256;
    #pragma unroll
    for (int l = 0; l < 16; l++) {
        int idx = l*256 + tid;
        ((float4*)ws)[idx] = ((const float4*)Sp)[idx];
    }
    __syncthreads();

    const int wid = tid >> 5, lane = tid & 31;
    for (int r = wid*8; r < wid*8 + 8; r++) {
        float* row = ws + r*256;
        float v[8];
        float mx = -1e30f;
        #pragma unroll
        for (int e2=0;e2<8;e2++){ v[e2] = row[lane + e2*32]; mx = fmaxf(mx, v[e2]); }
        #pragma unroll
        for (int o=16;o;o>>=1) mx = fmaxf(mx, __shfl_xor_sync(0xffffffffu, mx, o));
        float s = 0.f;
        #pragma unroll
        for (int e2=0;e2<8;e2++){ v[e2] = __expf(v[e2] - mx); s += v[e2]; }
        #pragma unroll
        for (int o=16;o;o>>=1) s += __shfl_xor_sync(0xffffffffu, s, o);
        float inv = 1.f / s;
        #pragma unroll
        for (int e2=0;e2<8;e2++) row[lane + e2*32] = v[e2]*inv;
    }
    __syncthreads();

    const int tx = tid & 15, ty = tid >> 4;  // 16x16, 4x4 per thread
    float acc[4][4];
    #pragma unroll
    for (int p=0;p<4;p++)
        #pragma unroll
        for (int q=0;q<4;q++) acc[p][q]=0.f;

    const float* Vp = g_V + (size_t)b*256*512 + h*64;
    for (int kbv = 0; kbv < 256; kbv += 32) {
        #pragma unroll
        for (int l=0;l<2;l++){
            int idx = l*256 + tid;
            int kk = idx >> 4, dq = idx & 15;
            float4 vv = *(const float4*)(Vp + (size_t)(kbv+kk)*512 + dq*4);
            *(float4*)(vs + kk*68 + dq*4) = vv;
        }
        __syncthreads();
        #pragma unroll
        for (int k=0;k<32;k++){
            float a0 = ws[(ty*4+0)*256 + kbv + k];
            float a1 = ws[(ty*4+1)*256 + kbv + k];
            float a2 = ws[(ty*4+2)*256 + kbv + k];
            float a3 = ws[(ty*4+3)*256 + kbv + k];
            float4 vv = *(float4*)(vs + k*68 + tx*4);
            acc[0][0] += a0*vv.x; acc[0][1] += a0*vv.y; acc[0][2] += a0*vv.z; acc[0][3] += a0*vv.w;
            acc[1][0] += a1*vv.x; acc[1][1] += a1*vv.y; acc[1][2] += a1*vv.z; acc[1][3] += a1*vv.w;
            acc[2][0] += a2*vv.x; acc[2][1] += a2*vv.y; acc[2][2] += a2*vv.z; acc[2][3] += a2*vv.w;
            acc[3][0] += a3*vv.x; acc[3][1] += a3*vv.y; acc[3][2] += a3*vv.z; acc[3][3] += a3*vv.w;
        }
        __syncthreads();
    }

    float* outp = hout + (size_t)(b*256 + i0)*512 + h*64;
    #pragma unroll
    for (int p=0;p<4;p++){
        int r = ty*4 + p;
        *(float4*)(outp + (size_t)r*512 + tx*4) =
            make_float4(acc[p][0], acc[p][1], acc[p][2], acc[p][3]);
    }
}

extern "C" void kernel_launch(void* const* d_in, const int* in_sizes, int n_in,
                              void* d_out, int out_size)
{
    const float* h  = (const float*)d_in[0];
    const float* e  = (const float*)d_in[1];
    const float* Wq = (const float*)d_in[2];
    const float* Wk = (const float*)d_in[3];
    const float* Wv = (const float*)d_in[4];
    const float* We = (const float*)d_in[5];
    float* outp  = (float*)d_out;
    float* h_out = outp;                               // [B,N,H*D]
    float* e_out = outp + (size_t)BB*NN*CC;            // [B,N,N,H*D]

    float *pQ, *pK, *pV;
    cudaGetSymbolAddress((void**)&pQ, g_Q);
    cudaGetSymbolAddress((void**)&pK, g_K);
    cudaGetSymbolAddress((void**)&pV, g_V);

    cudaFuncSetAttribute(softmax_av, cudaFuncAttributeMaxDynamicSharedMemorySize, 75776);

    const size_t gs = 2*32*136*4 + 1024;   // tiles (34816B) + 1KB row sums = 35840
    dim3 qg(4, 8);             // x = n-tiles (4), y = m-tiles (8) ; M=1024, N=512
    gemm_tf32<0,1><<<qg, 256, gs>>>(h, Wq, pQ);
    gemm_tf32<0,1><<<qg, 256, gs>>>(h, Wk, pK);
    gemm_tf32<0,1><<<qg, 256, gs>>>(h, Wv, pV);

    dim3 mg(4, 2048);          // x = n-tiles (4), y = m-tiles (2048)
    gemm_tf32<1,0><<<mg, 256, gs>>>(e, We, e_out);

    dim3 ag(4, 8, 4);
    softmax_av<<<ag, 256, 75776>>>(h_out);
}